// round 15
// baseline (speedup 1.0000x reference)
#include <cuda_runtime.h>

#define TE 8
#define NODES_MAX 50000

typedef unsigned long long ull;

__device__ float g_agg_s[(size_t)NODES_MAX * 64];
__device__ float g_agg_v[(size_t)NODES_MAX * 192];

__device__ __forceinline__ ull ffma2(ull a, ull b, ull c) {
  ull d;
  asm("fma.rn.f32x2 %0, %1, %2, %3;" : "=l"(d) : "l"(a), "l"(b), "l"(c));
  return d;
}
__device__ __forceinline__ ull pack2(float x) {
  ull d;
  asm("mov.b64 %0, {%1, %1};" : "=l"(d) : "f"(x));
  return d;
}
__device__ __forceinline__ void upk8(const ull* a, float* f) {
#pragma unroll
  for (int j = 0; j < 4; j++) {
    f[2 * j]     = __int_as_float((int)(unsigned)(a[j] & 0xffffffffull));
    f[2 * j + 1] = __int_as_float((int)(unsigned)(a[j] >> 32));
  }
}
__device__ __forceinline__ float sigm(float x) { return 1.0f / (1.0f + __expf(-x)); }

#define RSQRT3 0.5773502692f
#define INV1   0.0622573010f   // 1/sqrt(258)
#define INV2   0.0883883476f   // 1/sqrt(128)
#define INV0   0.0625f         // 1/sqrt(256)
#define INVU   0.0883883476f   // 1/sqrt(128)

#define ACC4W2(arrRow, wa, wb, A, B) do {                                      \
    ulonglong2 _r0 = *reinterpret_cast<const ulonglong2*>(arrRow);             \
    ulonglong2 _r1 = *reinterpret_cast<const ulonglong2*>((arrRow) + 4);       \
    (A)[0] = ffma2(_r0.x, (wa), (A)[0]);                                       \
    (B)[0] = ffma2(_r0.x, (wb), (B)[0]);                                       \
    (A)[1] = ffma2(_r0.y, (wa), (A)[1]);                                       \
    (B)[1] = ffma2(_r0.y, (wb), (B)[1]);                                       \
    (A)[2] = ffma2(_r1.x, (wa), (A)[2]);                                       \
    (B)[2] = ffma2(_r1.x, (wb), (B)[2]);                                       \
    (A)[3] = ffma2(_r1.y, (wa), (A)[3]);                                       \
    (B)[3] = ffma2(_r1.y, (wb), (B)[3]);                                       \
  } while (0)

// R=2 GEMM: thread owns output pair (2*o2, 2*o2+1); one LDG.64 per k.
// MLP=4 weight batching (R9-proven depth for 6 CTAs/SM); K multiple of 4.
template <int K, int LDW, int RS>
__device__ __forceinline__ void gemmR2(const float* __restrict__ W, int o2,
                                       const float* __restrict__ row,
                                       ull* accA, ull* accB) {
#pragma unroll 1
  for (int k0 = 0; k0 < K; k0 += 4) {
    float2 w[4];
#pragma unroll
    for (int j = 0; j < 4; j++)
      w[j] = __ldg(reinterpret_cast<const float2*>(W + (size_t)(k0 + j) * LDW) + o2);
#pragma unroll
    for (int j = 0; j < 4; j++) {
      ull wa = pack2(w[j].x), wb = pack2(w[j].y);
      ACC4W2(row + (size_t)(k0 + j) * RS, wa, wb, accA, accB);
    }
  }
}

// ---------------------------------------------------------------------------
// Edge kernel: 8 edges/CTA, 128 threads, 6 CTAs/SM, R=2, raw smem,
// float4 gathers. R9 role structure.
// ---------------------------------------------------------------------------
__global__ void __launch_bounds__(128, 6) edge_kernel(
    const float* __restrict__ node_s, const float* __restrict__ node_v,
    const float* __restrict__ eas, const float* __restrict__ eav,
    const float* __restrict__ add_feat,
    const float* __restrict__ Wss1, const float* __restrict__ Wvs1,
    const float* __restrict__ Wsv1, const float* __restrict__ Wvv1,
    const float* __restrict__ b1,
    const float* __restrict__ Wss2, const float* __restrict__ Wvs2,
    const float* __restrict__ Wsv2, const float* __restrict__ Wvv2,
    const float* __restrict__ b2,
    const int* __restrict__ senders, const int* __restrict__ receivers,
    int E)
{
  __shared__ __align__(16) float xs_rT[130][TE];
  __shared__ __align__(16) float d1T[128][TE];      // d1; m2-scalar exchange
  __shared__ __align__(16) float xvT[128][3][TE];
  __shared__ __align__(16) float ms_rT[64][TE];
  __shared__ __align__(16) float gT[64][TE];
  __shared__ __align__(16) float d2T[64][TE];
  __shared__ __align__(16) float mvT[64][3][TE];    // m1-scalar exchange
  __shared__ __align__(16) float pT[64][TE];
  __shared__ float asx[TE];
  __shared__ float avx[3][TE];
  __shared__ int sndx[TE], rcvx[TE];

  const int tid = threadIdx.x;
  const int e0 = blockIdx.x * TE;

  if (tid < TE) {
    int ge = e0 + tid;
    bool val = ge < E;
    sndx[tid] = val ? senders[ge] : 0;
    rcvx[tid] = val ? receivers[ge] : -1;
    asx[tid]  = val ? eas[ge] : 0.f;
#pragma unroll
    for (int i = 0; i < 3; i++) avx[i][tid] = val ? eav[ge * 3 + i] : 0.f;
  }
  __syncthreads();

  // float4 gather of xs (node_s halves): TE*32 chunks
  for (int idx = tid; idx < TE * 32; idx += 128) {
    int e = idx >> 5, c = idx & 31;
    int r = rcvx[e] < 0 ? 0 : rcvx[e];
    int node = (c < 16) ? sndx[e] : r;
    int s0 = (c < 16) ? (c * 4) : (64 + (c - 16) * 4);
    float4 v = __ldg(reinterpret_cast<const float4*>(node_s + (size_t)node * 64) +
                     (c & 15));
    xs_rT[s0 + 0][e] = v.x;
    xs_rT[s0 + 1][e] = v.y;
    xs_rT[s0 + 2][e] = v.z;
    xs_rT[s0 + 3][e] = v.w;
  }
  if (tid < TE * 2) {  // add_feat tail
    int e = tid >> 1, i = tid & 1;
    int ge = e0 + e;
    xs_rT[128 + i][e] = (ge < E) ? __ldg(add_feat + (size_t)ge * 2 + i) : 0.f;
  }
  // float4 gather of xv: TE*96 chunks
  for (int idx = tid; idx < TE * 96; idx += 128) {
    int e = idx / 96, c = idx - e * 96;
    int r = rcvx[e] < 0 ? 0 : rcvx[e];
    int node = (c < 48) ? sndx[e] : r;
    int j0 = (c < 48) ? (c * 4) : (192 + (c - 48) * 4);
    float4 v = __ldg(reinterpret_cast<const float4*>(node_v + (size_t)node * 192) +
                     (c % 48));
    float vv[4] = {v.x, v.y, v.z, v.w};
#pragma unroll
    for (int j = 0; j < 4; j++) {
      int g = j0 + j;
      xvT[g / 3][g % 3][e] = vv[j];
    }
  }
  __syncthreads();

  for (int t = tid; t < TE * 128; t += 128) {
    int v = t >> 3, e = t & 7;
    d1T[v][e] = (xvT[v][0][e] * avx[0][e] + xvT[v][1][e] * avx[1][e] +
                 xvT[v][2][e] * avx[2][e]) * RSQRT3;
  }
  __syncthreads();

  // ---- m1 scalar: grp0 = xs@Wss1, grp1 = d1@Wvs1 -> exchange (mvT) ----
  {
    const int grp = tid >> 6;
    const int o2 = tid & 63;
    float* exch = &mvT[0][0][0];
    ull accA[4] = {0,0,0,0}, accB[4] = {0,0,0,0};
    if (grp == 0) {
      gemmR2<128, 128, TE>(Wss1, o2, &xs_rT[0][0], accA, accB);
      float2 w0 = __ldg(reinterpret_cast<const float2*>(Wss1 + (size_t)128 * 128) + o2);
      float2 w1 = __ldg(reinterpret_cast<const float2*>(Wss1 + (size_t)129 * 128) + o2);
      ACC4W2(&xs_rT[128][0], pack2(w0.x), pack2(w0.y), accA, accB);
      ACC4W2(&xs_rT[129][0], pack2(w1.x), pack2(w1.y), accA, accB);
    } else {
      gemmR2<128, 128, TE>(Wvs1, o2, &d1T[0][0], accA, accB);
      float pa[8], pb[8]; upk8(accA, pa); upk8(accB, pb);
#pragma unroll
      for (int e = 0; e < TE; e++) {
        exch[(2 * o2) * TE + e] = pa[e];
        exch[(2 * o2 + 1) * TE + e] = pb[e];
      }
    }
    __syncthreads();
    if (grp == 0) {
      float pa[8], pb[8]; upk8(accA, pa); upk8(accB, pb);
      int oA = 2 * o2, oB = 2 * o2 + 1;
      float bA = __ldg(b1 + oA), bB = __ldg(b1 + oB);
      if (oA < 64) {
#pragma unroll
        for (int e = 0; e < TE; e++) {
          float a = asx[e];
          float s1 = (a * pa[e] + exch[oA * TE + e]) * INV1 + bA;
          ms_rT[oA][e] = s1 * sigm(s1);
          float s2 = (a * pb[e] + exch[oB * TE + e]) * INV1 + bB;
          ms_rT[oB][e] = s2 * sigm(s2);
        }
      } else {
#pragma unroll
        for (int e = 0; e < TE; e++) {
          float a = asx[e];
          gT[oA - 64][e] = sigm((a * pa[e] + exch[oA * TE + e]) * INV1 + bA);
          gT[oB - 64][e] = sigm((a * pb[e] + exch[oB * TE + e]) * INV1 + bB);
        }
      }
    }
  }
  __syncthreads();

  // ---- m1 vector: 4 roles x 32 threads x pair ----
  {
    const int role = tid >> 5;
    const int o2 = tid & 31;
    ull accA[4] = {0,0,0,0}, accB[4] = {0,0,0,0};
    if (role < 3) {
      gemmR2<128, 64, 3 * TE>(Wvv1, o2, &xvT[0][role][0], accA, accB);
    } else {
      gemmR2<128, 64, TE>(Wsv1, o2, &xs_rT[0][0], accA, accB);
      float2 w0 = __ldg(reinterpret_cast<const float2*>(Wsv1 + (size_t)128 * 64) + o2);
      float2 w1 = __ldg(reinterpret_cast<const float2*>(Wsv1 + (size_t)129 * 64) + o2);
      ACC4W2(&xs_rT[128][0], pack2(w0.x), pack2(w0.y), accA, accB);
      ACC4W2(&xs_rT[129][0], pack2(w1.x), pack2(w1.y), accA, accB);
      float pa[8], pb[8]; upk8(accA, pa); upk8(accB, pb);
#pragma unroll
      for (int e = 0; e < TE; e++) {
        pT[2 * o2][e] = pa[e];
        pT[2 * o2 + 1][e] = pb[e];
      }
    }
    __syncthreads();
    if (role < 3) {
      float qa[8], qb[8]; upk8(accA, qa); upk8(accB, qb);
      int oA = 2 * o2, oB = 2 * o2 + 1;
#pragma unroll
      for (int e = 0; e < TE; e++) {
        float a = asx[e];
        mvT[oA][role][e] = (pT[oA][e] * avx[role][e] + a * qa[e]) * gT[oA][e] * INV1;
        mvT[oB][role][e] = (pT[oB][e] * avx[role][e] + a * qb[e]) * gT[oB][e] * INV1;
      }
    }
  }
  __syncthreads();

  // d2
  for (int t = tid; t < TE * 64; t += 128) {
    int v = t >> 3, e = t & 7;
    d2T[v][e] = (mvT[v][0][e] * avx[0][e] + mvT[v][1][e] * avx[1][e] +
                 mvT[v][2][e] * avx[2][e]) * RSQRT3;
  }
  __syncthreads();

  // ---- m2 scalar: grp0 = ms@Wss2, grp1 = d2@Wvs2 -> exchange (d1T) ----
  {
    const int grp = tid >> 6;
    const int o2 = tid & 63;
    float* exch = &d1T[0][0];
    ull accA[4] = {0,0,0,0}, accB[4] = {0,0,0,0};
    if (grp == 0) {
      gemmR2<64, 128, TE>(Wss2, o2, &ms_rT[0][0], accA, accB);
    } else {
      gemmR2<64, 128, TE>(Wvs2, o2, &d2T[0][0], accA, accB);
      float pa[8], pb[8]; upk8(accA, pa); upk8(accB, pb);
#pragma unroll
      for (int e = 0; e < TE; e++) {
        exch[(2 * o2) * TE + e] = pa[e];
        exch[(2 * o2 + 1) * TE + e] = pb[e];
      }
    }
    __syncthreads();
    if (grp == 0) {
      float pa[8], pb[8]; upk8(accA, pa); upk8(accB, pb);
      int oA = 2 * o2, oB = 2 * o2 + 1;
      float bA = __ldg(b2 + oA), bB = __ldg(b2 + oB);
      if (oA < 64) {
#pragma unroll
        for (int e = 0; e < TE; e++) {
          int r = rcvx[e];
          if (r < 0) continue;
          float a = asx[e];
          float s1 = (a * pa[e] + exch[oA * TE + e]) * INV2 + bA;
          float s2 = (a * pb[e] + exch[oB * TE + e]) * INV2 + bB;
          atomicAdd(g_agg_s + (size_t)r * 64 + oA, s1 * sigm(s1));
          atomicAdd(g_agg_s + (size_t)r * 64 + oB, s2 * sigm(s2));
        }
      } else {
#pragma unroll
        for (int e = 0; e < TE; e++) {
          float a = asx[e];
          gT[oA - 64][e] = sigm((a * pa[e] + exch[oA * TE + e]) * INV2 + bA);
          gT[oB - 64][e] = sigm((a * pb[e] + exch[oB * TE + e]) * INV2 + bB);
        }
      }
    }
  }
  __syncthreads();

  // ---- m2 vector: 4 roles x 32 x pair; atomic scatter ----
  {
    const int role = tid >> 5;
    const int o2 = tid & 31;
    ull accA[4] = {0,0,0,0}, accB[4] = {0,0,0,0};
    if (role < 3) {
      gemmR2<64, 64, 3 * TE>(Wvv2, o2, &mvT[0][role][0], accA, accB);
    } else {
      gemmR2<64, 64, TE>(Wsv2, o2, &ms_rT[0][0], accA, accB);
      float pa[8], pb[8]; upk8(accA, pa); upk8(accB, pb);
#pragma unroll
      for (int e = 0; e < TE; e++) {
        pT[2 * o2][e] = pa[e];
        pT[2 * o2 + 1][e] = pb[e];
      }
    }
    __syncthreads();
    if (role < 3) {
      float qa[8], qb[8]; upk8(accA, qa); upk8(accB, qb);
      int oA = 2 * o2, oB = 2 * o2 + 1;
#pragma unroll
      for (int e = 0; e < TE; e++) {
        int r = rcvx[e];
        if (r < 0) continue;
        float a = asx[e];
        atomicAdd(g_agg_v + (size_t)r * 192 + oA * 3 + role,
                  (pT[oA][e] * avx[role][e] + a * qa[e]) * gT[oA][e] * INV2);
        atomicAdd(g_agg_v + (size_t)r * 192 + oB * 3 + role,
                  (pT[oB][e] * avx[role][e] + a * qb[e]) * gT[oB][e] * INV2);
      }
    }
  }
}

// ---------------------------------------------------------------------------
// Node kernel: R9 structure + float4 gathers (MLP=4 gemm).
// ---------------------------------------------------------------------------
__global__ void __launch_bounds__(128, 6) node_kernel(
    const float* __restrict__ node_s, const float* __restrict__ node_v,
    const float* __restrict__ nas, const float* __restrict__ nav,
    const float* __restrict__ Wss0, const float* __restrict__ Wvs0,
    const float* __restrict__ Wsv0, const float* __restrict__ Wvv0,
    const float* __restrict__ b0,
    const float* __restrict__ Wssu, const float* __restrict__ Wvsu,
    const float* __restrict__ Wsvu, const float* __restrict__ Wvvu,
    const float* __restrict__ bu,
    float* __restrict__ out, int N)
{
  __shared__ __align__(16) float xs_rT[128][TE];
  __shared__ __align__(16) float d1T[128][TE];
  __shared__ __align__(16) float xvT[128][3][TE];
  __shared__ __align__(16) float hs_rT[64][TE];
  __shared__ __align__(16) float gT[64][TE];
  __shared__ __align__(16) float d2T[64][TE];
  __shared__ __align__(16) float hvT[64][3][TE];
  __shared__ __align__(16) float pT[64][TE];
  __shared__ float asx[TE], avx[3][TE];

  const int tid = threadIdx.x;
  const int n0 = blockIdx.x * TE;

  if (tid < TE) {
    int n = n0 + tid;
    bool val = n < N;
    asx[tid] = val ? nas[n] : 0.f;
#pragma unroll
    for (int i = 0; i < 3; i++) avx[i][tid] = val ? nav[n * 3 + i] : 0.f;
  }
  __syncthreads();

  for (int idx = tid; idx < TE * 32; idx += 128) {
    int e = idx >> 5, c = idx & 31;
    int n = n0 + e; if (n >= N) n = 0;
    const float* base = (c < 16) ? (node_s + (size_t)n * 64)
                                 : (g_agg_s + (size_t)n * 64);
    int s0 = (c < 16) ? (c * 4) : (64 + (c - 16) * 4);
    float4 v = __ldg(reinterpret_cast<const float4*>(base) + (c & 15));
    xs_rT[s0 + 0][e] = v.x;
    xs_rT[s0 + 1][e] = v.y;
    xs_rT[s0 + 2][e] = v.z;
    xs_rT[s0 + 3][e] = v.w;
  }
  for (int idx = tid; idx < TE * 96; idx += 128) {
    int e = idx / 96, c = idx - e * 96;
    int n = n0 + e; if (n >= N) n = 0;
    const float* base = (c < 48) ? (node_v + (size_t)n * 192)
                                 : (g_agg_v + (size_t)n * 192);
    int j0 = (c < 48) ? (c * 4) : (192 + (c - 48) * 4);
    float4 v = __ldg(reinterpret_cast<const float4*>(base) + (c % 48));
    float vv[4] = {v.x, v.y, v.z, v.w};
#pragma unroll
    for (int j = 0; j < 4; j++) {
      int g = j0 + j;
      xvT[g / 3][g % 3][e] = vv[j];
    }
  }
  __syncthreads();

  for (int t = tid; t < TE * 128; t += 128) {
    int v = t >> 3, e = t & 7;
    d1T[v][e] = (xvT[v][0][e] * avx[0][e] + xvT[v][1][e] * avx[1][e] +
                 xvT[v][2][e] * avx[2][e]) * RSQRT3;
  }
  __syncthreads();

  // ---- u0 scalar ----
  {
    const int grp = tid >> 6;
    const int o2 = tid & 63;
    float* exch = &hvT[0][0][0];
    ull accA[4] = {0,0,0,0}, accB[4] = {0,0,0,0};
    if (grp == 0) {
      gemmR2<128, 128, TE>(Wss0, o2, &xs_rT[0][0], accA, accB);
    } else {
      gemmR2<128, 128, TE>(Wvs0, o2, &d1T[0][0], accA, accB);
      float pa[8], pb[8]; upk8(accA, pa); upk8(accB, pb);
#pragma unroll
      for (int e = 0; e < TE; e++) {
        exch[(2 * o2) * TE + e] = pa[e];
        exch[(2 * o2 + 1) * TE + e] = pb[e];
      }
    }
    __syncthreads();
    if (grp == 0) {
      float pa[8], pb[8]; upk8(accA, pa); upk8(accB, pb);
      int oA = 2 * o2, oB = 2 * o2 + 1;
      float bA = __ldg(b0 + oA), bB = __ldg(b0 + oB);
      if (oA < 64) {
#pragma unroll
        for (int e = 0; e < TE; e++) {
          float a = asx[e];
          float s1 = (a * pa[e] + exch[oA * TE + e]) * INV0 + bA;
          hs_rT[oA][e] = s1 * sigm(s1);
          float s2 = (a * pb[e] + exch[oB * TE + e]) * INV0 + bB;
          hs_rT[oB][e] = s2 * sigm(s2);
        }
      } else {
#pragma unroll
        for (int e = 0; e < TE; e++) {
          float a = asx[e];
          gT[oA - 64][e] = sigm((a * pa[e] + exch[oA * TE + e]) * INV0 + bA);
          gT[oB - 64][e] = sigm((a * pb[e] + exch[oB * TE + e]) * INV0 + bB);
        }
      }
    }
  }
  __syncthreads();

  // ---- u0 vector ----
  {
    const int role = tid >> 5;
    const int o2 = tid & 31;
    ull accA[4] = {0,0,0,0}, accB[4] = {0,0,0,0};
    if (role < 3) {
      gemmR2<128, 64, 3 * TE>(Wvv0, o2, &xvT[0][role][0], accA, accB);
    } else {
      gemmR2<128, 64, TE>(Wsv0, o2, &xs_rT[0][0], accA, accB);
      float pa[8], pb[8]; upk8(accA, pa); upk8(accB, pb);
#pragma unroll
      for (int e = 0; e < TE; e++) {
        pT[2 * o2][e] = pa[e];
        pT[2 * o2 + 1][e] = pb[e];
      }
    }
    __syncthreads();
    if (role < 3) {
      float qa[8], qb[8]; upk8(accA, qa); upk8(accB, qb);
      int oA = 2 * o2, oB = 2 * o2 + 1;
#pragma unroll
      for (int e = 0; e < TE; e++) {
        float a = asx[e];
        hvT[oA][role][e] = (pT[oA][e] * avx[role][e] + a * qa[e]) * gT[oA][e] * INV0;
        hvT[oB][role][e] = (pT[oB][e] * avx[role][e] + a * qb[e]) * gT[oB][e] * INV0;
      }
    }
  }
  __syncthreads();

  for (int t = tid; t < TE * 64; t += 128) {
    int v = t >> 3, e = t & 7;
    d2T[v][e] = (hvT[v][0][e] * avx[0][e] + hvT[v][1][e] * avx[1][e] +
                 hvT[v][2][e] * avx[2][e]) * RSQRT3;
  }
  __syncthreads();

  // ---- u1 scalar ----
  {
    const int role = tid >> 5;
    const int o2 = tid & 31;
    float* exch = &gT[0][0];
    ull accA[4] = {0,0,0,0}, accB[4] = {0,0,0,0};
    if (role == 1) {
      gemmR2<64, 64, TE>(Wvsu, o2, &d2T[0][0], accA, accB);
      float pa[8], pb[8]; upk8(accA, pa); upk8(accB, pb);
#pragma unroll
      for (int e = 0; e < TE; e++) {
        exch[(2 * o2) * TE + e] = pa[e];
        exch[(2 * o2 + 1) * TE + e] = pb[e];
      }
    } else if (role == 0) {
      gemmR2<64, 64, TE>(Wssu, o2, &hs_rT[0][0], accA, accB);
    }
    __syncthreads();
    if (role == 0) {
      float pa[8], pb[8]; upk8(accA, pa); upk8(accB, pb);
      int oA = 2 * o2, oB = 2 * o2 + 1;
      float bA = __ldg(bu + oA), bB = __ldg(bu + oB);
#pragma unroll
      for (int e = 0; e < TE; e++) {
        int n = n0 + e;
        if (n >= N) continue;
        float a = asx[e];
        out[(size_t)n * 256 + oA] =
            __ldg(node_s + (size_t)n * 64 + oA) + (a * pa[e] + exch[oA * TE + e]) * INVU + bA;
        out[(size_t)n * 256 + oB] =
            __ldg(node_s + (size_t)n * 64 + oB) + (a * pb[e] + exch[oB * TE + e]) * INVU + bB;
      }
    }
  }
  __syncthreads();

  // ---- u1 vector ----
  {
    const int role = tid >> 5;
    const int o2 = tid & 31;
    ull accA[4] = {0,0,0,0}, accB[4] = {0,0,0,0};
    if (role < 3) {
      gemmR2<64, 64, 3 * TE>(Wvvu, o2, &hvT[0][role][0], accA, accB);
    } else {
      gemmR2<64, 64, TE>(Wsvu, o2, &hs_rT[0][0], accA, accB);
      float pa[8], pb[8]; upk8(accA, pa); upk8(accB, pb);
#pragma unroll
      for (int e = 0; e < TE; e++) {
        pT[2 * o2][e] = pa[e];
        pT[2 * o2 + 1][e] = pb[e];
      }
    }
    __syncthreads();
    if (role < 3) {
      float qa[8], qb[8]; upk8(accA, qa); upk8(accB, qb);
      int oA = 2 * o2, oB = 2 * o2 + 1;
#pragma unroll
      for (int e = 0; e < TE; e++) {
        int n = n0 + e;
        if (n >= N) continue;
        float a = asx[e];
        out[(size_t)n * 256 + 64 + oA * 3 + role] =
            __ldg(node_v + (size_t)n * 192 + oA * 3 + role) +
            (pT[oA][e] * avx[role][e] + a * qa[e]) * INVU;
        out[(size_t)n * 256 + 64 + oB * 3 + role] =
            __ldg(node_v + (size_t)n * 192 + oB * 3 + role) +
            (pT[oB][e] * avx[role][e] + a * qb[e]) * INVU;
      }
    }
  }
}

extern "C" void kernel_launch(void* const* d_in, const int* in_sizes, int n_in,
                              void* d_out, int out_size) {
  const float* node_s = (const float*)d_in[0];
  const float* node_v = (const float*)d_in[1];
  const float* nas    = (const float*)d_in[2];
  const float* nav    = (const float*)d_in[3];
  const float* eas    = (const float*)d_in[4];
  const float* eav    = (const float*)d_in[5];
  const float* add_f  = (const float*)d_in[6];
  const float* m1Wss  = (const float*)d_in[7];
  const float* m1Wvs  = (const float*)d_in[8];
  const float* m1Wsv  = (const float*)d_in[9];
  const float* m1Wvv  = (const float*)d_in[10];
  const float* m1b    = (const float*)d_in[11];
  const float* m2Wss  = (const float*)d_in[12];
  const float* m2Wvs  = (const float*)d_in[13];
  const float* m2Wsv  = (const float*)d_in[14];
  const float* m2Wvv  = (const float*)d_in[15];
  const float* m2b    = (const float*)d_in[16];
  const float* u0Wss  = (const float*)d_in[17];
  const float* u0Wvs  = (const float*)d_in[18];
  const float* u0Wsv  = (const float*)d_in[19];
  const float* u0Wvv  = (const float*)d_in[20];
  const float* u0b    = (const float*)d_in[21];
  const float* u1Wss  = (const float*)d_in[22];
  const float* u1Wvs  = (const float*)d_in[23];
  const float* u1Wsv  = (const float*)d_in[24];
  const float* u1Wvv  = (const float*)d_in[25];
  const float* u1b    = (const float*)d_in[26];
  const int* senders   = (const int*)d_in[27];
  const int* receivers = (const int*)d_in[28];

  int E = in_sizes[27];
  int N = in_sizes[0] / 64;

  void* p_s = nullptr; void* p_v = nullptr;
  cudaGetSymbolAddress(&p_s, g_agg_s);
  cudaGetSymbolAddress(&p_v, g_agg_v);
  cudaMemsetAsync(p_s, 0, (size_t)N * 64 * sizeof(float));
  cudaMemsetAsync(p_v, 0, (size_t)N * 192 * sizeof(float));

  edge_kernel<<<(E + TE - 1) / TE, 128>>>(
      node_s, node_v, eas, eav, add_f,
      m1Wss, m1Wvs, m1Wsv, m1Wvv, m1b,
      m2Wss, m2Wvs, m2Wsv, m2Wvv, m2b,
      senders, receivers, E);
  node_kernel<<<(N + TE - 1) / TE, 128>>>(
      node_s, node_v, nas, nav,
      u0Wss, u0Wvs, u0Wsv, u0Wvv, u0b,
      u1Wss, u1Wvs, u1Wsv, u1Wvv, u1b,
      (float*)d_out, N);
}

// round 16
// speedup vs baseline: 1.1191x; 1.1191x over previous
#include <cuda_runtime.h>

#define TE 8
#define NODES_MAX 50000

typedef unsigned long long ull;

__device__ float g_agg_s[(size_t)NODES_MAX * 64];
__device__ float g_agg_v[(size_t)NODES_MAX * 192];

__device__ __forceinline__ ull ffma2(ull a, ull b, ull c) {
  ull d;
  asm("fma.rn.f32x2 %0, %1, %2, %3;" : "=l"(d) : "l"(a), "l"(b), "l"(c));
  return d;
}
__device__ __forceinline__ ull pack2(float x) {
  ull d;
  asm("mov.b64 %0, {%1, %1};" : "=l"(d) : "f"(x));
  return d;
}
__device__ __forceinline__ void upk8(const ull* a, float* f) {
#pragma unroll
  for (int j = 0; j < 4; j++) {
    f[2 * j]     = __int_as_float((int)(unsigned)(a[j] & 0xffffffffull));
    f[2 * j + 1] = __int_as_float((int)(unsigned)(a[j] >> 32));
  }
}
__device__ __forceinline__ float sigm(float x) { return 1.0f / (1.0f + __expf(-x)); }

#define RSQRT3 0.5773502692f
#define INV1   0.0622573010f   // 1/sqrt(258)
#define INV2   0.0883883476f   // 1/sqrt(128)
#define INV0   0.0625f         // 1/sqrt(256)
#define INVU   0.0883883476f   // 1/sqrt(128)

// one smem row (8 edges) feeds TWO output columns
#define ACC4W2(arrRow, wa, wb, A, B) do {                                      \
    ulonglong2 _r0 = *reinterpret_cast<const ulonglong2*>(arrRow);             \
    ulonglong2 _r1 = *reinterpret_cast<const ulonglong2*>((arrRow) + 4);       \
    (A)[0] = ffma2(_r0.x, (wa), (A)[0]);                                       \
    (B)[0] = ffma2(_r0.x, (wb), (B)[0]);                                       \
    (A)[1] = ffma2(_r0.y, (wa), (A)[1]);                                       \
    (B)[1] = ffma2(_r0.y, (wb), (B)[1]);                                       \
    (A)[2] = ffma2(_r1.x, (wa), (A)[2]);                                       \
    (B)[2] = ffma2(_r1.x, (wb), (B)[2]);                                       \
    (A)[3] = ffma2(_r1.y, (wa), (A)[3]);                                       \
    (B)[3] = ffma2(_r1.y, (wb), (B)[3]);                                       \
  } while (0)

// R=2 GEMM: thread owns output pair (2*o2, 2*o2+1); one LDG.64 per k.
// MLP=4 weight batching (proven depth at 6 CTAs/SM); K multiple of 4.
template <int K, int LDW, int RS>
__device__ __forceinline__ void gemmR2(const float* __restrict__ W, int o2,
                                       const float* __restrict__ row,
                                       ull* accA, ull* accB) {
#pragma unroll 1
  for (int k0 = 0; k0 < K; k0 += 4) {
    float2 w[4];
#pragma unroll
    for (int j = 0; j < 4; j++)
      w[j] = __ldg(reinterpret_cast<const float2*>(W + (size_t)(k0 + j) * LDW) + o2);
#pragma unroll
    for (int j = 0; j < 4; j++) {
      ull wa = pack2(w[j].x), wb = pack2(w[j].y);
      ACC4W2(row + (size_t)(k0 + j) * RS, wa, wb, accA, accB);
    }
  }
}

// ---------------------------------------------------------------------------
// Edge kernel: 8 edges/CTA, 128 threads, 6 CTAs/SM, R=2, raw smem (a_s in
// epilogues). Warp-uniform roles throughout. (R9 winner, verbatim.)
// ---------------------------------------------------------------------------
__global__ void __launch_bounds__(128, 6) edge_kernel(
    const float* __restrict__ node_s, const float* __restrict__ node_v,
    const float* __restrict__ eas, const float* __restrict__ eav,
    const float* __restrict__ add_feat,
    const float* __restrict__ Wss1, const float* __restrict__ Wvs1,
    const float* __restrict__ Wsv1, const float* __restrict__ Wvv1,
    const float* __restrict__ b1,
    const float* __restrict__ Wss2, const float* __restrict__ Wvs2,
    const float* __restrict__ Wsv2, const float* __restrict__ Wvv2,
    const float* __restrict__ b2,
    const int* __restrict__ senders, const int* __restrict__ receivers,
    int E)
{
  __shared__ __align__(16) float xs_rT[130][TE];    // raw xs
  __shared__ __align__(16) float d1T[128][TE];      // d1; m2-scalar exchange
  __shared__ __align__(16) float xvT[128][3][TE];   // raw xv
  __shared__ __align__(16) float ms_rT[64][TE];     // raw silu output
  __shared__ __align__(16) float gT[64][TE];
  __shared__ __align__(16) float d2T[64][TE];
  __shared__ __align__(16) float mvT[64][3][TE];    // raw mv; m1-scalar exchange
  __shared__ __align__(16) float pT[64][TE];
  __shared__ float asx[TE];
  __shared__ float avx[3][TE];
  __shared__ int sndx[TE], rcvx[TE];

  const int tid = threadIdx.x;
  const int e0 = blockIdx.x * TE;

  if (tid < TE) {
    int ge = e0 + tid;
    bool val = ge < E;
    sndx[tid] = val ? senders[ge] : 0;
    rcvx[tid] = val ? receivers[ge] : -1;
    asx[tid]  = val ? eas[ge] : 0.f;
#pragma unroll
    for (int i = 0; i < 3; i++) avx[i][tid] = val ? eav[ge * 3 + i] : 0.f;
  }
  __syncthreads();

  // gather raw xs, xv (scalar coalesced — proven best)
  for (int idx = tid; idx < TE * 130; idx += 128) {
    int e = idx / 130, s = idx - e * 130;
    int r = rcvx[e] < 0 ? 0 : rcvx[e];
    float v;
    if (s < 64)       v = __ldg(node_s + (size_t)sndx[e] * 64 + s);
    else if (s < 128) v = __ldg(node_s + (size_t)r * 64 + (s - 64));
    else {
      int ge = e0 + e;
      v = (ge < E) ? __ldg(add_feat + (size_t)ge * 2 + (s - 128)) : 0.f;
    }
    xs_rT[s][e] = v;
  }
  for (int idx = tid; idx < TE * 384; idx += 128) {
    int e = idx / 384, j = idx - e * 384;
    int r = rcvx[e] < 0 ? 0 : rcvx[e];
    float v = (j < 192) ? __ldg(node_v + (size_t)sndx[e] * 192 + j)
                        : __ldg(node_v + (size_t)r * 192 + (j - 192));
    xvT[j / 3][j % 3][e] = v;
  }
  __syncthreads();

  // d1 = (xv_raw . av)/sqrt3
  for (int t = tid; t < TE * 128; t += 128) {
    int v = t >> 3, e = t & 7;
    d1T[v][e] = (xvT[v][0][e] * avx[0][e] + xvT[v][1][e] * avx[1][e] +
                 xvT[v][2][e] * avx[2][e]) * RSQRT3;
  }
  __syncthreads();

  // ---- m1 scalar: grp0 = xs_r@Wss1 (raw), grp1 = d1@Wvs1 -> exchange ----
  {
    const int grp = tid >> 6;
    const int o2 = tid & 63;
    float* exch = &mvT[0][0][0];    // 1536 >= 128*8
    ull accA[4] = {0,0,0,0}, accB[4] = {0,0,0,0};
    if (grp == 0) {
      gemmR2<128, 128, TE>(Wss1, o2, &xs_rT[0][0], accA, accB);
      float2 w0 = __ldg(reinterpret_cast<const float2*>(Wss1 + (size_t)128 * 128) + o2);
      float2 w1 = __ldg(reinterpret_cast<const float2*>(Wss1 + (size_t)129 * 128) + o2);
      ACC4W2(&xs_rT[128][0], pack2(w0.x), pack2(w0.y), accA, accB);
      ACC4W2(&xs_rT[129][0], pack2(w1.x), pack2(w1.y), accA, accB);
    } else {
      gemmR2<128, 128, TE>(Wvs1, o2, &d1T[0][0], accA, accB);
      float pa[8], pb[8]; upk8(accA, pa); upk8(accB, pb);
#pragma unroll
      for (int e = 0; e < TE; e++) {
        exch[(2 * o2) * TE + e] = pa[e];
        exch[(2 * o2 + 1) * TE + e] = pb[e];
      }
    }
    __syncthreads();
    if (grp == 0) {
      float pa[8], pb[8]; upk8(accA, pa); upk8(accB, pb);
      int oA = 2 * o2, oB = 2 * o2 + 1;
      float bA = __ldg(b1 + oA), bB = __ldg(b1 + oB);
      if (oA < 64) {
#pragma unroll
        for (int e = 0; e < TE; e++) {
          float a = asx[e];
          float s1 = (a * pa[e] + exch[oA * TE + e]) * INV1 + bA;
          ms_rT[oA][e] = s1 * sigm(s1);
          float s2 = (a * pb[e] + exch[oB * TE + e]) * INV1 + bB;
          ms_rT[oB][e] = s2 * sigm(s2);
        }
      } else {
#pragma unroll
        for (int e = 0; e < TE; e++) {
          float a = asx[e];
          gT[oA - 64][e] = sigm((a * pa[e] + exch[oA * TE + e]) * INV1 + bA);
          gT[oB - 64][e] = sigm((a * pb[e] + exch[oB * TE + e]) * INV1 + bB);
        }
      }
    }
  }
  __syncthreads();

  // ---- m1 vector: 4 roles x 32 threads x pair; raw q, a_s in epilogue ----
  {
    const int role = tid >> 5;
    const int o2 = tid & 31;
    ull accA[4] = {0,0,0,0}, accB[4] = {0,0,0,0};
    if (role < 3) {
      gemmR2<128, 64, 3 * TE>(Wvv1, o2, &xvT[0][role][0], accA, accB);
    } else {
      gemmR2<128, 64, TE>(Wsv1, o2, &xs_rT[0][0], accA, accB);
      float2 w0 = __ldg(reinterpret_cast<const float2*>(Wsv1 + (size_t)128 * 64) + o2);
      float2 w1 = __ldg(reinterpret_cast<const float2*>(Wsv1 + (size_t)129 * 64) + o2);
      ACC4W2(&xs_rT[128][0], pack2(w0.x), pack2(w0.y), accA, accB);
      ACC4W2(&xs_rT[129][0], pack2(w1.x), pack2(w1.y), accA, accB);
      float pa[8], pb[8]; upk8(accA, pa); upk8(accB, pb);
#pragma unroll
      for (int e = 0; e < TE; e++) {
        pT[2 * o2][e] = pa[e];
        pT[2 * o2 + 1][e] = pb[e];
      }
    }
    __syncthreads();
    if (role < 3) {
      float qa[8], qb[8]; upk8(accA, qa); upk8(accB, qb);
      int oA = 2 * o2, oB = 2 * o2 + 1;
#pragma unroll
      for (int e = 0; e < TE; e++) {
        float a = asx[e];
        mvT[oA][role][e] = (pT[oA][e] * avx[role][e] + a * qa[e]) * gT[oA][e] * INV1;
        mvT[oB][role][e] = (pT[oB][e] * avx[role][e] + a * qb[e]) * gT[oB][e] * INV1;
      }
    }
  }
  __syncthreads();

  // d2 = (mv_raw . av)/sqrt3
  for (int t = tid; t < TE * 64; t += 128) {
    int v = t >> 3, e = t & 7;
    d2T[v][e] = (mvT[v][0][e] * avx[0][e] + mvT[v][1][e] * avx[1][e] +
                 mvT[v][2][e] * avx[2][e]) * RSQRT3;
  }
  __syncthreads();

  // ---- m2 scalar: grp0 = ms_r@Wss2 (raw), grp1 = d2@Wvs2 -> exch(d1T) ----
  {
    const int grp = tid >> 6;
    const int o2 = tid & 63;
    float* exch = &d1T[0][0];       // 1024 = 128*8, retired
    ull accA[4] = {0,0,0,0}, accB[4] = {0,0,0,0};
    if (grp == 0) {
      gemmR2<64, 128, TE>(Wss2, o2, &ms_rT[0][0], accA, accB);
    } else {
      gemmR2<64, 128, TE>(Wvs2, o2, &d2T[0][0], accA, accB);
      float pa[8], pb[8]; upk8(accA, pa); upk8(accB, pb);
#pragma unroll
      for (int e = 0; e < TE; e++) {
        exch[(2 * o2) * TE + e] = pa[e];
        exch[(2 * o2 + 1) * TE + e] = pb[e];
      }
    }
    __syncthreads();
    if (grp == 0) {
      float pa[8], pb[8]; upk8(accA, pa); upk8(accB, pb);
      int oA = 2 * o2, oB = 2 * o2 + 1;
      float bA = __ldg(b2 + oA), bB = __ldg(b2 + oB);
      if (oA < 64) {
#pragma unroll
        for (int e = 0; e < TE; e++) {
          int r = rcvx[e];
          if (r < 0) continue;
          float a = asx[e];
          float s1 = (a * pa[e] + exch[oA * TE + e]) * INV2 + bA;
          float s2 = (a * pb[e] + exch[oB * TE + e]) * INV2 + bB;
          atomicAdd(g_agg_s + (size_t)r * 64 + oA, s1 * sigm(s1));
          atomicAdd(g_agg_s + (size_t)r * 64 + oB, s2 * sigm(s2));
        }
      } else {
#pragma unroll
        for (int e = 0; e < TE; e++) {
          float a = asx[e];
          gT[oA - 64][e] = sigm((a * pa[e] + exch[oA * TE + e]) * INV2 + bA);
          gT[oB - 64][e] = sigm((a * pb[e] + exch[oB * TE + e]) * INV2 + bB);
        }
      }
    }
  }
  __syncthreads();

  // ---- m2 vector: 4 roles x 32 x pair; atomic scatter ----
  {
    const int role = tid >> 5;
    const int o2 = tid & 31;
    ull accA[4] = {0,0,0,0}, accB[4] = {0,0,0,0};
    if (role < 3) {
      gemmR2<64, 64, 3 * TE>(Wvv2, o2, &mvT[0][role][0], accA, accB);
    } else {
      gemmR2<64, 64, TE>(Wsv2, o2, &ms_rT[0][0], accA, accB);
      float pa[8], pb[8]; upk8(accA, pa); upk8(accB, pb);
#pragma unroll
      for (int e = 0; e < TE; e++) {
        pT[2 * o2][e] = pa[e];
        pT[2 * o2 + 1][e] = pb[e];
      }
    }
    __syncthreads();
    if (role < 3) {
      float qa[8], qb[8]; upk8(accA, qa); upk8(accB, qb);
      int oA = 2 * o2, oB = 2 * o2 + 1;
#pragma unroll
      for (int e = 0; e < TE; e++) {
        int r = rcvx[e];
        if (r < 0) continue;
        float a = asx[e];
        atomicAdd(g_agg_v + (size_t)r * 192 + oA * 3 + role,
                  (pT[oA][e] * avx[role][e] + a * qa[e]) * gT[oA][e] * INV2);
        atomicAdd(g_agg_v + (size_t)r * 192 + oB * 3 + role,
                  (pT[oB][e] * avx[role][e] + a * qb[e]) * gT[oB][e] * INV2);
      }
    }
  }
}

// ---------------------------------------------------------------------------
// Node kernel: same raw-smem R=2 structure for u0/u1. (R9 winner, verbatim.)
// ---------------------------------------------------------------------------
__global__ void __launch_bounds__(128, 6) node_kernel(
    const float* __restrict__ node_s, const float* __restrict__ node_v,
    const float* __restrict__ nas, const float* __restrict__ nav,
    const float* __restrict__ Wss0, const float* __restrict__ Wvs0,
    const float* __restrict__ Wsv0, const float* __restrict__ Wvv0,
    const float* __restrict__ b0,
    const float* __restrict__ Wssu, const float* __restrict__ Wvsu,
    const float* __restrict__ Wsvu, const float* __restrict__ Wvvu,
    const float* __restrict__ bu,
    float* __restrict__ out, int N)
{
  __shared__ __align__(16) float xs_rT[128][TE];
  __shared__ __align__(16) float d1T[128][TE];
  __shared__ __align__(16) float xvT[128][3][TE];
  __shared__ __align__(16) float hs_rT[64][TE];
  __shared__ __align__(16) float gT[64][TE];       // u1-scalar exchange
  __shared__ __align__(16) float d2T[64][TE];
  __shared__ __align__(16) float hvT[64][3][TE];   // u0-scalar exchange
  __shared__ __align__(16) float pT[64][TE];
  __shared__ float asx[TE], avx[3][TE];

  const int tid = threadIdx.x;
  const int n0 = blockIdx.x * TE;

  if (tid < TE) {
    int n = n0 + tid;
    bool val = n < N;
    asx[tid] = val ? nas[n] : 0.f;
#pragma unroll
    for (int i = 0; i < 3; i++) avx[i][tid] = val ? nav[n * 3 + i] : 0.f;
  }
  __syncthreads();

  for (int idx = tid; idx < TE * 128; idx += 128) {
    int e = idx >> 7, s = idx & 127;
    int n = n0 + e; if (n >= N) n = 0;
    xs_rT[s][e] = (s < 64) ? __ldg(node_s + (size_t)n * 64 + s)
                           : g_agg_s[(size_t)n * 64 + (s - 64)];
  }
  for (int idx = tid; idx < TE * 384; idx += 128) {
    int e = idx / 384, j = idx - e * 384;
    int n = n0 + e; if (n >= N) n = 0;
    float v = (j < 192) ? __ldg(node_v + (size_t)n * 192 + j)
                        : g_agg_v[(size_t)n * 192 + (j - 192)];
    xvT[j / 3][j % 3][e] = v;
  }
  __syncthreads();

  for (int t = tid; t < TE * 128; t += 128) {
    int v = t >> 3, e = t & 7;
    d1T[v][e] = (xvT[v][0][e] * avx[0][e] + xvT[v][1][e] * avx[1][e] +
                 xvT[v][2][e] * avx[2][e]) * RSQRT3;
  }
  __syncthreads();

  // ---- u0 scalar ----
  {
    const int grp = tid >> 6;
    const int o2 = tid & 63;
    float* exch = &hvT[0][0][0];
    ull accA[4] = {0,0,0,0}, accB[4] = {0,0,0,0};
    if (grp == 0) {
      gemmR2<128, 128, TE>(Wss0, o2, &xs_rT[0][0], accA, accB);
    } else {
      gemmR2<128, 128, TE>(Wvs0, o2, &d1T[0][0], accA, accB);
      float pa[8], pb[8]; upk8(accA, pa); upk8(accB, pb);
#pragma unroll
      for (int e = 0; e < TE; e++) {
        exch[(2 * o2) * TE + e] = pa[e];
        exch[(2 * o2 + 1) * TE + e] = pb[e];
      }
    }
    __syncthreads();
    if (grp == 0) {
      float pa[8], pb[8]; upk8(accA, pa); upk8(accB, pb);
      int oA = 2 * o2, oB = 2 * o2 + 1;
      float bA = __ldg(b0 + oA), bB = __ldg(b0 + oB);
      if (oA < 64) {
#pragma unroll
        for (int e = 0; e < TE; e++) {
          float a = asx[e];
          float s1 = (a * pa[e] + exch[oA * TE + e]) * INV0 + bA;
          hs_rT[oA][e] = s1 * sigm(s1);
          float s2 = (a * pb[e] + exch[oB * TE + e]) * INV0 + bB;
          hs_rT[oB][e] = s2 * sigm(s2);
        }
      } else {
#pragma unroll
        for (int e = 0; e < TE; e++) {
          float a = asx[e];
          gT[oA - 64][e] = sigm((a * pa[e] + exch[oA * TE + e]) * INV0 + bA);
          gT[oB - 64][e] = sigm((a * pb[e] + exch[oB * TE + e]) * INV0 + bB);
        }
      }
    }
  }
  __syncthreads();

  // ---- u0 vector ----
  {
    const int role = tid >> 5;
    const int o2 = tid & 31;
    ull accA[4] = {0,0,0,0}, accB[4] = {0,0,0,0};
    if (role < 3) {
      gemmR2<128, 64, 3 * TE>(Wvv0, o2, &xvT[0][role][0], accA, accB);
    } else {
      gemmR2<128, 64, TE>(Wsv0, o2, &xs_rT[0][0], accA, accB);
      float pa[8], pb[8]; upk8(accA, pa); upk8(accB, pb);
#pragma unroll
      for (int e = 0; e < TE; e++) {
        pT[2 * o2][e] = pa[e];
        pT[2 * o2 + 1][e] = pb[e];
      }
    }
    __syncthreads();
    if (role < 3) {
      float qa[8], qb[8]; upk8(accA, qa); upk8(accB, qb);
      int oA = 2 * o2, oB = 2 * o2 + 1;
#pragma unroll
      for (int e = 0; e < TE; e++) {
        float a = asx[e];
        hvT[oA][role][e] = (pT[oA][e] * avx[role][e] + a * qa[e]) * gT[oA][e] * INV0;
        hvT[oB][role][e] = (pT[oB][e] * avx[role][e] + a * qb[e]) * gT[oB][e] * INV0;
      }
    }
  }
  __syncthreads();

  for (int t = tid; t < TE * 64; t += 128) {
    int v = t >> 3, e = t & 7;
    d2T[v][e] = (hvT[v][0][e] * avx[0][e] + hvT[v][1][e] * avx[1][e] +
                 hvT[v][2][e] * avx[2][e]) * RSQRT3;
  }
  __syncthreads();

  // ---- u1 scalar (64 outs): role0 Wssu (raw hs), role1 Wvsu -> exch(gT) ----
  {
    const int role = tid >> 5;
    const int o2 = tid & 31;
    float* exch = &gT[0][0];
    ull accA[4] = {0,0,0,0}, accB[4] = {0,0,0,0};
    if (role == 1) {
      gemmR2<64, 64, TE>(Wvsu, o2, &d2T[0][0], accA, accB);
      float pa[8], pb[8]; upk8(accA, pa); upk8(accB, pb);
#pragma unroll
      for (int e = 0; e < TE; e++) {
        exch[(2 * o2) * TE + e] = pa[e];
        exch[(2 * o2 + 1) * TE + e] = pb[e];
      }
    } else if (role == 0) {
      gemmR2<64, 64, TE>(Wssu, o2, &hs_rT[0][0], accA, accB);
    }
    __syncthreads();
    if (role == 0) {
      float pa[8], pb[8]; upk8(accA, pa); upk8(accB, pb);
      int oA = 2 * o2, oB = 2 * o2 + 1;
      float bA = __ldg(bu + oA), bB = __ldg(bu + oB);
#pragma unroll
      for (int e = 0; e < TE; e++) {
        int n = n0 + e;
        if (n >= N) continue;
        float a = asx[e];
        out[(size_t)n * 256 + oA] =
            __ldg(node_s + (size_t)n * 64 + oA) + (a * pa[e] + exch[oA * TE + e]) * INVU + bA;
        out[(size_t)n * 256 + oB] =
            __ldg(node_s + (size_t)n * 64 + oB) + (a * pb[e] + exch[oB * TE + e]) * INVU + bB;
      }
    }
  }
  __syncthreads();

  // ---- u1 vector: 4 roles x 32 x pair; residual writes ----
  {
    const int role = tid >> 5;
    const int o2 = tid & 31;
    ull accA[4] = {0,0,0,0}, accB[4] = {0,0,0,0};
    if (role < 3) {
      gemmR2<64, 64, 3 * TE>(Wvvu, o2, &hvT[0][role][0], accA, accB);
    } else {
      gemmR2<64, 64, TE>(Wsvu, o2, &hs_rT[0][0], accA, accB);
      float pa[8], pb[8]; upk8(accA, pa); upk8(accB, pb);
#pragma unroll
      for (int e = 0; e < TE; e++) {
        pT[2 * o2][e] = pa[e];
        pT[2 * o2 + 1][e] = pb[e];
      }
    }
    __syncthreads();
    if (role < 3) {
      float qa[8], qb[8]; upk8(accA, qa); upk8(accB, qb);
      int oA = 2 * o2, oB = 2 * o2 + 1;
#pragma unroll
      for (int e = 0; e < TE; e++) {
        int n = n0 + e;
        if (n >= N) continue;
        float a = asx[e];
        out[(size_t)n * 256 + 64 + oA * 3 + role] =
            __ldg(node_v + (size_t)n * 192 + oA * 3 + role) +
            (pT[oA][e] * avx[role][e] + a * qa[e]) * INVU;
        out[(size_t)n * 256 + 64 + oB * 3 + role] =
            __ldg(node_v + (size_t)n * 192 + oB * 3 + role) +
            (pT[oB][e] * avx[role][e] + a * qb[e]) * INVU;
      }
    }
  }
}

extern "C" void kernel_launch(void* const* d_in, const int* in_sizes, int n_in,
                              void* d_out, int out_size) {
  const float* node_s = (const float*)d_in[0];
  const float* node_v = (const float*)d_in[1];
  const float* nas    = (const float*)d_in[2];
  const float* nav    = (const float*)d_in[3];
  const float* eas    = (const float*)d_in[4];
  const float* eav    = (const float*)d_in[5];
  const float* add_f  = (const float*)d_in[6];
  const float* m1Wss  = (const float*)d_in[7];
  const float* m1Wvs  = (const float*)d_in[8];
  const float* m1Wsv  = (const float*)d_in[9];
  const float* m1Wvv  = (const float*)d_in[10];
  const float* m1b    = (const float*)d_in[11];
  const float* m2Wss  = (const float*)d_in[12];
  const float* m2Wvs  = (const float*)d_in[13];
  const float* m2Wsv  = (const float*)d_in[14];
  const float* m2Wvv  = (const float*)d_in[15];
  const float* m2b    = (const float*)d_in[16];
  const float* u0Wss  = (const float*)d_in[17];
  const float* u0Wvs  = (const float*)d_in[18];
  const float* u0Wsv  = (const float*)d_in[19];
  const float* u0Wvv  = (const float*)d_in[20];
  const float* u0b    = (const float*)d_in[21];
  const float* u1Wss  = (const float*)d_in[22];
  const float* u1Wvs  = (const float*)d_in[23];
  const float* u1Wsv  = (const float*)d_in[24];
  const float* u1Wvv  = (const float*)d_in[25];
  const float* u1b    = (const float*)d_in[26];
  const int* senders   = (const int*)d_in[27];
  const int* receivers = (const int*)d_in[28];

  int E = in_sizes[27];
  int N = in_sizes[0] / 64;

  void* p_s = nullptr; void* p_v = nullptr;
  cudaGetSymbolAddress(&p_s, g_agg_s);
  cudaGetSymbolAddress(&p_v, g_agg_v);
  cudaMemsetAsync(p_s, 0, (size_t)N * 64 * sizeof(float));
  cudaMemsetAsync(p_v, 0, (size_t)N * 192 * sizeof(float));

  edge_kernel<<<(E + TE - 1) / TE, 128>>>(
      node_s, node_v, eas, eav, add_f,
      m1Wss, m1Wvs, m1Wsv, m1Wvv, m1b,
      m2Wss, m2Wvs, m2Wsv, m2Wvv, m2b,
      senders, receivers, E);
  node_kernel<<<(N + TE - 1) / TE, 128>>>(
      node_s, node_v, nas, nav,
      u0Wss, u0Wvs, u0Wsv, u0Wvv, u0b,
      u1Wss, u1Wvs, u1Wsv, u1Wvv, u1b,
      (float*)d_out, N);
}